// round 4
// baseline (speedup 1.0000x reference)
#include <cuda_runtime.h>
#include <cstdint>

// ReceptiveFieldLayer: J=4, R=10, pad=3.
// out[b,c,i,j] = relu(max over 2-3 taps/axis of feat[b,x,y,c]), c in {0,1,2}
// Input : [16, 256, 256, 64] f32 NHWC.  Output: [16, 3, 1024, 1024] f32.
//
// Fused single kernel, TMA bulk-store write path:
//  - CTA = 4 output rows x 1024 cols x 3 channels.
//  - Patch: 3 feature rows x 258 cols x 3 ch in SMEM (zero-padded edges).
//  - 256 threads: thread q computes output cols 4q..4q+3 for 4 rows x 3 ch
//    (R1's 3x3->4x4 max scheme), STS.128 into a 48KB SMEM output tile.
//  - One elected thread issues 3 x 16KB cp.async.bulk SMEM->GMEM stores
//    (output rows are fully contiguous per (b,ch)), removing ~394K STG.128
//    from the LSU/L1 path chip-wide.

#define SH_W 258
#define SMEM_OUT_BYTES (3 * 4 * 1024 * 4)                 // 49152
#define SMEM_PATCH_BYTES (3 * 3 * SH_W * 4)               // 9288
#define SMEM_TOTAL (SMEM_OUT_BYTES + SMEM_PATCH_BYTES)    // 58440

__device__ __forceinline__ uint32_t smem_u32(const void* p) {
    uint32_t a;
    asm("{ .reg .u64 t; cvta.to.shared.u64 t, %1; cvt.u32.u64 %0, t; }" : "=r"(a) : "l"(p));
    return a;
}

__global__ __launch_bounds__(256, 3)
void rf_fused_tma_kernel(const float* __restrict__ in, float* __restrict__ out) {
    extern __shared__ float smem[];
    float* sm_out = smem;                                   // [3][4][1024]
    float (*sh)[3][SH_W] = (float (*)[3][SH_W])(smem + 3 * 4 * 1024);  // [3ch][3rows][258]

    const int i0 = blockIdx.x * 4;       // output row base
    const int b  = blockIdx.y;
    const int fq = i0 >> 2;              // feature row base
    const int tid = threadIdx.x;

    // ---- Load 3-channel, 3-row x 258-col feature patch (zero-padded) ----
    for (int pos = tid; pos < 3 * SH_W; pos += 256) {
        int sx = pos / SH_W;             // 0..2 -> feature row fq-1+sx
        int sy = pos - sx * SH_W;        // 0..257 -> feature col sy-1
        int fx = fq - 1 + sx;
        int fy = sy - 1;
        float x = 0.f, y = 0.f, z = 0.f;
        if ((unsigned)fx < 256u && (unsigned)fy < 256u) {
            const float4 v = __ldg(reinterpret_cast<const float4*>(
                in + ((((size_t)b * 256 + fx) * 256 + fy) << 6)));
            x = v.x; y = v.y; z = v.z;
        }
        sh[0][sx][sy] = x;
        sh[1][sx][sy] = y;
        sh[2][sx][sy] = z;
    }
    __syncthreads();

    // ---- Thread q: output cols 4q..4q+3, rows i0..i0+3, 3 channels ----
    const int q = tid;                   // shared cols q..q+2

    #pragma unroll
    for (int ch = 0; ch < 3; ch++) {
        float a00 = sh[ch][0][q], a01 = sh[ch][0][q + 1], a02 = sh[ch][0][q + 2];
        float a10 = sh[ch][1][q], a11 = sh[ch][1][q + 1], a12 = sh[ch][1][q + 2];
        float a20 = sh[ch][2][q], a21 = sh[ch][2][q + 1], a22 = sh[ch][2][q + 2];

        // per-row column maxes: a = {q,q+1}, b = {q+1,q+2}, c = {q,q+1,q+2}
        float c0a = fmaxf(a00, a01), c0b = fmaxf(a01, a02), c0c = fmaxf(c0a, a02);
        float c1a = fmaxf(a10, a11), c1b = fmaxf(a11, a12), c1c = fmaxf(c1a, a12);
        float c2a = fmaxf(a20, a21), c2b = fmaxf(a21, a22), c2c = fmaxf(c2a, a22);

        // row combos (relu folded): row 0 -> {s0,s1}; rows 1,2 -> {s0,s1,s2}; row 3 -> {s1,s2}
        float r01_a  = fmaxf(fmaxf(c0a, c1a), 0.f);
        float r01_c  = fmaxf(fmaxf(c0c, c1c), 0.f);
        float r01_b  = fmaxf(fmaxf(c0b, c1b), 0.f);
        float r012_a = fmaxf(r01_a, c2a);
        float r012_c = fmaxf(r01_c, c2c);
        float r012_b = fmaxf(r01_b, c2b);
        float r12_a  = fmaxf(fmaxf(c1a, c2a), 0.f);
        float r12_c  = fmaxf(fmaxf(c1c, c2c), 0.f);
        float r12_b  = fmaxf(fmaxf(c1b, c2b), 0.f);

        float4 v0 = make_float4(r01_a,  r01_c,  r01_c,  r01_b);
        float4 v1 = make_float4(r012_a, r012_c, r012_c, r012_b);
        float4 v3 = make_float4(r12_a,  r12_c,  r12_c,  r12_b);

        float4* o = reinterpret_cast<float4*>(sm_out + (ch * 4) * 1024 + q * 4);
        o[0]   = v0;       // row 0   (+1024 floats = +256 float4)
        o[256] = v1;       // row 1
        o[512] = v1;       // row 2
        o[768] = v3;       // row 3
    }
    __syncthreads();

    // ---- Bulk store: 3 contiguous 16KB copies (one per channel) ----
    if (tid == 0) {
        asm volatile("fence.proxy.async.shared::cta;" ::: "memory");
        #pragma unroll
        for (int ch = 0; ch < 3; ch++) {
            float* gptr = out + ((((size_t)b * 3 + ch) * 1024) + (size_t)i0) * 1024;
            uint32_t sptr = smem_u32(sm_out + ch * 4 * 1024);
            asm volatile(
                "cp.async.bulk.global.shared::cta.bulk_group [%0], [%1], %2;"
                :: "l"(gptr), "r"(sptr), "n"(16384) : "memory");
        }
        asm volatile("cp.async.bulk.commit_group;" ::: "memory");
        asm volatile("cp.async.bulk.wait_group.read 0;" ::: "memory");
    }
}

extern "C" void kernel_launch(void* const* d_in, const int* in_sizes, int n_in,
                              void* d_out, int out_size) {
    const float* in = (const float*)d_in[0];
    float* out = (float*)d_out;

    cudaFuncSetAttribute(rf_fused_tma_kernel,
                         cudaFuncAttributeMaxDynamicSharedMemorySize, SMEM_TOTAL);

    dim3 grid(1024 / 4, 16);   // 256 row-tiles x 16 batches
    rf_fused_tma_kernel<<<grid, 256, SMEM_TOTAL>>>(in, out);
}